// round 15
// baseline (speedup 1.0000x reference)
#include <cuda_runtime.h>
#include <cuda_bf16.h>
#include <cuda_fp16.h>
#include <math.h>
#include <stdint.h>

#define B_   64
#define L_   2048
#define E_   512
#define Q_   256
#define NEGV -1000000000.0f
#define EPS_ 1e-5f
#define NSPLIT 64

// ---------------------------------------------------------------------------
// device scratch (no allocations allowed)
// ---------------------------------------------------------------------------
__device__ float g_qproj[B_ * E_];
__device__ float g_ctx_part[B_ * NSPLIT * E_];
__device__ __align__(16) __half g_Wt16[E_ * E_];   // W1[:E]^T fp16 [e][k]
__device__ int g_dummy_sink;

// ---------------------------------------------------------------------------
// PTX helpers
// ---------------------------------------------------------------------------
__device__ __forceinline__ uint32_t smem_u32_of(const void* p) {
    uint32_t a;
    asm("{ .reg .u64 t; cvta.to.shared.u64 t, %1; cvt.u32.u64 %0, t; }"
        : "=r"(a) : "l"(p));
    return a;
}

__device__ __forceinline__ void ldsm4(uint32_t* r, uint32_t addr) {
    asm volatile("ldmatrix.sync.aligned.m8n8.x4.shared.b16 {%0,%1,%2,%3}, [%4];"
                 : "=r"(r[0]), "=r"(r[1]), "=r"(r[2]), "=r"(r[3]) : "r"(addr));
}

__device__ __forceinline__ void mma_f16(float* c, const uint32_t* a, const uint32_t* b) {
    asm volatile(
        "mma.sync.aligned.m16n8k16.row.col.f32.f16.f16.f32 "
        "{%0,%1,%2,%3}, {%4,%5,%6,%7}, {%8,%9}, {%0,%1,%2,%3};"
        : "+f"(c[0]), "+f"(c[1]), "+f"(c[2]), "+f"(c[3])
        : "r"(a[0]), "r"(a[1]), "r"(a[2]), "r"(a[3]), "r"(b[0]), "r"(b[1]));
}

#define CP_ASYNC16(dst, src) \
    asm volatile("cp.async.cg.shared.global [%0], [%1], 16;" :: "r"(dst), "l"(src) : "memory")
#define CP_COMMIT()  asm volatile("cp.async.commit_group;" ::: "memory")
#define CP_WAITG0()  asm volatile("cp.async.wait_group 0;" ::: "memory")
#define BAR_PAIR(id) asm volatile("bar.sync %0, 64;" :: "r"(id) : "memory")

// ---------------------------------------------------------------------------
// MUFU tanh
// ---------------------------------------------------------------------------
__device__ __forceinline__ float tanh_mufu(float x) {
    float xc = fminf(fmaxf(x, -9.0f), 9.0f);
    float e;
    asm("ex2.approx.f32 %0, %1;" : "=f"(e) : "f"(xc * 2.885390081777927f)); // e^{2x}
    float r;
    asm("rcp.approx.f32 %0, %1;" : "=f"(r) : "f"(e + 1.0f));
    return (e - 1.0f) * r;
}

// ---------------------------------------------------------------------------
// Kernel 0: coalesced SMEM tile transpose + fp16 convert of W1[:E]
// grid (16,16), block 256 (32x8)
// ---------------------------------------------------------------------------
__global__ void wprep_kernel(const float* __restrict__ W1) {
    __shared__ float tile[32][33];
    int tx = threadIdx.x & 31;
    int ty = threadIdx.x >> 5;                 // 0..7
    int e0 = blockIdx.x * 32;
    int k0 = blockIdx.y * 32;
#pragma unroll
    for (int j = 0; j < 32; j += 8)
        tile[ty + j][tx] = W1[(size_t)(k0 + ty + j) * E_ + e0 + tx];
    __syncthreads();
#pragma unroll
    for (int j = 0; j < 32; j += 8)
        g_Wt16[(size_t)(e0 + ty + j) * E_ + k0 + tx] =
            __float2half_rn(tile[tx][ty + j]);
}

// ---------------------------------------------------------------------------
// Kernel 1: qproj — grid (16, 8): W1[E:] read 8x not 64x
// ---------------------------------------------------------------------------
__global__ void qproj_kernel(const float* __restrict__ query,
                             const float* __restrict__ W1,
                             const float* __restrict__ b1) {
    __shared__ float qs[8][Q_];
    int tid = threadIdx.x;                      // 256
    int b0 = blockIdx.y * 8;
    int e  = blockIdx.x * 32 + (tid & 31);
    int bi = tid >> 5;
    {
        int r = tid >> 5;
        int c = (tid & 31) * 8;
#pragma unroll
        for (int u = 0; u < 8; u++)
            qs[r][c + u] = query[(b0 + r) * Q_ + c + u];
    }
    __syncthreads();
    float acc = b1[e];
#pragma unroll 8
    for (int q = 0; q < Q_; q++)
        acc = fmaf(qs[bi][q], W1[(size_t)(E_ + q) * E_ + e], acc);
    g_qproj[(b0 + bi) * E_ + e] = acc;
}

// ---------------------------------------------------------------------------
// Dummy pad kernel (positions logits at profiled launch index 3)
// ---------------------------------------------------------------------------
__global__ void dummy_pad_kernel() {
    if (threadIdx.x == 0) g_dummy_sink = 1;
}

// ---------------------------------------------------------------------------
// Kernel 2: tensor-core logits — UNCHANGED from R14 champion.
// ---------------------------------------------------------------------------
#define BM 64
#define NTILE 128

#define SM_W    0                       // [4 pair][2 stage][32 n][128B] = 32768
#define W_PAIR  8192
#define W_STAGE 4096
#define SM_A    32768                   // [64 rows][1024B] fp16 resident = 65536
#define SM_QV   98304                   // 512 floats
#define SM_VV   100352                  // 512 floats
#define SM_RED  102400                  // 256 floats
#define SMEM_GEMM 103424

__global__ void __launch_bounds__(256, 2)
logits_mma_kernel(const float* __restrict__ enc,
                  const float* __restrict__ v,
                  const int* __restrict__ length,
                  float* __restrict__ logits) {
    extern __shared__ char smem[];
    uint32_t smem_b = smem_u32_of(smem);
    const int tid  = threadIdx.x;
    const int lane = tid & 31;
    const int wid  = tid >> 5;
    const int mg   = wid & 1;
    const int ng   = wid >> 1;

    const int bid = blockIdx.x;     // 2048 CTAs
    const int b   = bid >> 5;
    const int l0  = (bid & 31) * BM;

    if (l0 >= length[b]) return;

    const int t = tid & 63;
    const int tng = tid >> 6;
    const __half* wsrc0 = g_Wt16 + (size_t)(tng * 32 + (t >> 1)) * E_ + (t & 1) * 32;
    uint32_t wdsts[4];
#pragma unroll
    for (int i = 0; i < 4; i++) {
        uint32_t u = (uint32_t)((t & 1) * 4 + i);
        wdsts[i] = smem_b + SM_W + (uint32_t)tng * W_PAIR + (uint32_t)(t >> 1) * 128
                 + ((u ^ ((uint32_t)(t >> 1) & 7)) << 4);
    }

#pragma unroll
    for (int i = 0; i < 4; i++)
        CP_ASYNC16(wdsts[i], wsrc0 + i * 8);
    CP_COMMIT();

    float* qv = reinterpret_cast<float*>(smem + SM_QV);
    float* vv = reinterpret_cast<float*>(smem + SM_VV);
    qv[tid]       = g_qproj[b * E_ + tid];
    qv[tid + 256] = g_qproj[b * E_ + tid + 256];
    vv[tid]       = v[tid];
    vv[tid + 256] = v[tid + 256];

    const float* Ag = enc + ((size_t)b * L_ + l0) * E_;
#pragma unroll
    for (int i = 0; i < 32; i++) {
        int idx = i * 256 + tid;
        int row = idx >> 7;
        int f4  = idx & 127;
        float4 a = *reinterpret_cast<const float4*>(Ag + (size_t)row * E_ + f4 * 4);
        __half2 h0 = __floats2half2_rn(a.x, a.y);
        __half2 h1 = __floats2half2_rn(a.z, a.w);
        uint32_t off = (uint32_t)(row * 1024)
                     + ((uint32_t)(((f4 >> 1) ^ (row & 7))) << 4) + (f4 & 1) * 8;
        *reinterpret_cast<__half2*>(smem + SM_A + off)     = h0;
        *reinterpret_cast<__half2*>(smem + SM_A + off + 4) = h1;
    }
    __syncthreads();

    const int  s7     = lane & 7;
    const int  lane16 = lane >> 4;
    const int  lane8  = (lane >> 3) & 1;
    const int  arow0  = mg * 32 + (lane & 15);
    const uint32_t abase0 = smem_b + SM_A + (uint32_t)arow0 * 1024;
    const uint32_t abase1 = abase0 + 16 * 1024;
    const int  nrl    = (lane & 7) + (lane16 << 3);
    const uint32_t wpair = smem_b + SM_W + (uint32_t)ng * W_PAIR;
    const uint32_t woff0 = (uint32_t)nrl * 128;
    const uint32_t woff1 = woff0 + 16 * 128;

    float acc[2][4][4];
    float lg[2][2] = {{0.f, 0.f}, {0.f, 0.f}};

    for (int nt = 0; nt < 4; nt++) {
#pragma unroll
        for (int mf = 0; mf < 2; mf++)
#pragma unroll
            for (int nf = 0; nf < 4; nf++)
#pragma unroll
                for (int e = 0; e < 4; e++) acc[mf][nf][e] = 0.0f;

#pragma unroll
        for (int kc = 0; kc < 8; kc++) {
            const int s = nt * 8 + kc;

            CP_WAITG0();
            BAR_PAIR(1 + ng);

            if (s + 1 < 32) {
                const int sn = s + 1;
                const uint32_t srcoff = (uint32_t)(sn >> 3) * 65536u
                                      + (uint32_t)(sn & 7) * 64u;
                const uint32_t stoff = (uint32_t)(sn & 1) * W_STAGE;
#pragma unroll
                for (int i = 0; i < 4; i++)
                    CP_ASYNC16(wdsts[i] + stoff, wsrc0 + srcoff + i * 8);
                CP_COMMIT();
            }

            const uint32_t wBase = wpair + (uint32_t)(s & 1) * W_STAGE;

#pragma unroll
            for (int ks = 0; ks < 4; ks++) {
                uint32_t aF0[4], aF1[4];
                {
                    uint32_t c = (uint32_t)(kc * 8 + ks * 2 + lane16);
                    uint32_t sw = (c ^ (uint32_t)s7) << 4;
                    ldsm4(aF0, abase0 + sw);
                    ldsm4(aF1, abase1 + sw);
                }
                uint32_t b0[4], b1[4];
                {
                    uint32_t c = (uint32_t)(ks * 2 + lane8);
                    uint32_t sw = (c ^ (uint32_t)(nrl & 7)) << 4;
                    ldsm4(b0, wBase + woff0 + sw);
                    ldsm4(b1, wBase + woff1 + sw);
                }
                mma_f16(acc[0][0], aF0, b0);
                mma_f16(acc[0][1], aF0, b0 + 2);
                mma_f16(acc[0][2], aF0, b1);
                mma_f16(acc[0][3], aF0, b1 + 2);
                mma_f16(acc[1][0], aF1, b0);
                mma_f16(acc[1][1], aF1, b0 + 2);
                mma_f16(acc[1][2], aF1, b1);
                mma_f16(acc[1][3], aF1, b1 + 2);
            }
        }

        {
            const int colb = nt * NTILE + ng * 32 + (lane & 3) * 2;
#pragma unroll
            for (int mf = 0; mf < 2; mf++) {
#pragma unroll
                for (int nf = 0; nf < 4; nf++) {
                    int col = colb + nf * 8;
                    float q0 = qv[col], q1 = qv[col + 1];
                    float w0 = vv[col], w1 = vv[col + 1];
                    lg[mf][0] += tanh_mufu(acc[mf][nf][0] + q0) * w0
                               + tanh_mufu(acc[mf][nf][1] + q1) * w1;
                    lg[mf][1] += tanh_mufu(acc[mf][nf][2] + q0) * w0
                               + tanh_mufu(acc[mf][nf][3] + q1) * w1;
                }
            }
        }
    }

    float* red = reinterpret_cast<float*>(smem + SM_RED);
#pragma unroll
    for (int mf = 0; mf < 2; mf++)
#pragma unroll
        for (int h = 0; h < 2; h++) {
            float x = lg[mf][h];
            x += __shfl_xor_sync(0xffffffffu, x, 1);
            x += __shfl_xor_sync(0xffffffffu, x, 2);
            lg[mf][h] = x;
        }
    if ((lane & 3) == 0) {
        int r = mg * 32 + (lane >> 2);
        red[ng * 64 + r]      = lg[0][0];
        red[ng * 64 + r + 8]  = lg[0][1];
        red[ng * 64 + r + 16] = lg[1][0];
        red[ng * 64 + r + 24] = lg[1][1];
    }
    __syncthreads();
    if (tid < 64) {
        logits[(size_t)b * L_ + l0 + tid] =
            red[tid] + red[64 + tid] + red[128 + tid] + red[192 + tid];
    }
}

// ---------------------------------------------------------------------------
// Kernel 3: masked softmax in place — 1024 threads (loop depth 2)
// ---------------------------------------------------------------------------
__global__ void softmax_kernel(float* __restrict__ att,
                               const int* __restrict__ length) {
    int b = blockIdx.x;
    int n = length[b];
    float* row = att + (size_t)b * L_;
    int tid = threadIdx.x;                 // 1024
    __shared__ float red[32];

    float x0 = row[tid];
    float x1 = row[tid + 1024];
    float m = NEGV;
    if (tid < n) m = x0;
    if (tid + 1024 < n) m = fmaxf(m, x1);
#pragma unroll
    for (int o = 16; o > 0; o >>= 1) m = fmaxf(m, __shfl_xor_sync(0xffffffffu, m, o));
    if ((tid & 31) == 0) red[tid >> 5] = m;
    __syncthreads();
    if (tid < 32) {
        float mm = red[tid];
#pragma unroll
        for (int o = 16; o > 0; o >>= 1) mm = fmaxf(mm, __shfl_xor_sync(0xffffffffu, mm, o));
        red[tid] = mm;
    }
    __syncthreads();
    m = red[0];
    __syncthreads();

    float e0 = (tid < n) ? expf(x0 - m) : 0.0f;
    float e1 = (tid + 1024 < n) ? expf(x1 - m) : 0.0f;
    float s = e0 + e1;
#pragma unroll
    for (int o = 16; o > 0; o >>= 1) s += __shfl_xor_sync(0xffffffffu, s, o);
    if ((tid & 31) == 0) red[tid >> 5] = s;
    __syncthreads();
    if (tid < 32) {
        float ss = red[tid];
#pragma unroll
        for (int o = 16; o > 0; o >>= 1) ss += __shfl_xor_sync(0xffffffffu, ss, o);
        red[tid] = ss;
    }
    __syncthreads();
    s = red[0];

    float inv = 1.0f / (s + EPS_);
    row[tid]        = e0 * inv;
    row[tid + 1024] = e1 * inv;
}

// ---------------------------------------------------------------------------
// Kernel 4: context partials (fp32 enc), NSPLIT=64 (32 rows/split)
// ---------------------------------------------------------------------------
__global__ void ctx_partial_kernel(const float* __restrict__ enc,
                                   const float* __restrict__ att,
                                   const int* __restrict__ length) {
    int s = blockIdx.x;                    // 0..63
    int b = blockIdx.y;
    int t = threadIdx.x;                   // 128
    int n = length[b];
    int lbeg = s * (L_ / NSPLIT);
    int lend = lbeg + (L_ / NSPLIT);
    if (lend > n) lend = n;

    const float4* encb = reinterpret_cast<const float4*>(enc + (size_t)b * L_ * E_);
    const float* attb = att + (size_t)b * L_;
    float4 acc = make_float4(0.f, 0.f, 0.f, 0.f);
    int l = lbeg;
    for (; l + 4 <= lend; l += 4) {
#pragma unroll
        for (int u = 0; u < 4; u++) {
            float a = attb[l + u];
            float4 r = encb[(size_t)(l + u) * 128 + t];
            acc.x = fmaf(a, r.x, acc.x);
            acc.y = fmaf(a, r.y, acc.y);
            acc.z = fmaf(a, r.z, acc.z);
            acc.w = fmaf(a, r.w, acc.w);
        }
    }
    for (; l < lend; l++) {
        float a = attb[l];
        float4 r = encb[(size_t)l * 128 + t];
        acc.x = fmaf(a, r.x, acc.x);
        acc.y = fmaf(a, r.y, acc.y);
        acc.z = fmaf(a, r.z, acc.z);
        acc.w = fmaf(a, r.w, acc.w);
    }
    float4* outp = reinterpret_cast<float4*>(g_ctx_part + ((size_t)(b * NSPLIT + s)) * E_);
    outp[t] = acc;
}

// ---------------------------------------------------------------------------
// Kernel 5: reduce partials -> context
// ---------------------------------------------------------------------------
__global__ void ctx_reduce_kernel(float* __restrict__ context) {
    int b = blockIdx.x;
    int t = threadIdx.x;                   // 128
    float4 a = make_float4(0.f, 0.f, 0.f, 0.f);
#pragma unroll 8
    for (int s = 0; s < NSPLIT; s++) {
        const float4* p = reinterpret_cast<const float4*>(
            g_ctx_part + ((size_t)(b * NSPLIT + s)) * E_);
        float4 r = p[t];
        a.x += r.x; a.y += r.y; a.z += r.z; a.w += r.w;
    }
    reinterpret_cast<float4*>(context + (size_t)b * E_)[t] = a;
}

// ---------------------------------------------------------------------------
// launch
// ---------------------------------------------------------------------------
extern "C" void kernel_launch(void* const* d_in, const int* in_sizes, int n_in,
                              void* d_out, int out_size) {
    const float* enc   = (const float*)d_in[0];   // [B,L,E]
    const float* query = (const float*)d_in[1];   // [B,Q]
    const int*   len   = (const int*)  d_in[2];   // [B]
    const float* W1    = (const float*)d_in[3];   // [E+Q,E]
    const float* b1    = (const float*)d_in[4];   // [E]
    const float* v     = (const float*)d_in[5];   // [E]

    float* context = (float*)d_out;               // [B,E]
    float* att     = (float*)d_out + B_ * E_;     // [B,L]

    cudaFuncSetAttribute(logits_mma_kernel,
                         cudaFuncAttributeMaxDynamicSharedMemorySize, SMEM_GEMM);

    {
        dim3 g(16, 16);
        wprep_kernel<<<g, 256>>>(W1);                    // idx 0
    }
    {
        dim3 g(16, 8);
        qproj_kernel<<<g, 256>>>(query, W1, b1);         // idx 1
    }
    dummy_pad_kernel<<<1, 32>>>();                       // idx 2 (profiler pad)
    logits_mma_kernel<<<(B_ * L_) / BM, 256, SMEM_GEMM>>>(enc, v, len, att);  // idx 3
    softmax_kernel<<<B_, 1024>>>(att, len);              // idx 4
    {
        dim3 g(NSPLIT, B_);
        ctx_partial_kernel<<<g, 128>>>(enc, att, len);   // idx 5
    }
    ctx_reduce_kernel<<<B_, 128>>>(context);             // idx 6
}

// round 16
// speedup vs baseline: 1.0426x; 1.0426x over previous
#include <cuda_runtime.h>
#include <cuda_bf16.h>
#include <cuda_fp16.h>
#include <math.h>
#include <stdint.h>

#define B_   64
#define L_   2048
#define E_   512
#define Q_   256
#define NEGV -1000000000.0f
#define EPS_ 1e-5f
#define NSPLIT 32

// ---------------------------------------------------------------------------
// device scratch (no allocations allowed)
// ---------------------------------------------------------------------------
__device__ float g_qproj[B_ * E_];
__device__ float g_ctx_part[B_ * NSPLIT * E_];
__device__ __align__(16) __half g_Wt16[E_ * E_];   // W1[:E]^T fp16 [e][k]
__device__ int g_dummy_sink;

// ---------------------------------------------------------------------------
// PTX helpers
// ---------------------------------------------------------------------------
__device__ __forceinline__ uint32_t smem_u32_of(const void* p) {
    uint32_t a;
    asm("{ .reg .u64 t; cvta.to.shared.u64 t, %1; cvt.u32.u64 %0, t; }"
        : "=r"(a) : "l"(p));
    return a;
}

__device__ __forceinline__ void ldsm4(uint32_t* r, uint32_t addr) {
    asm volatile("ldmatrix.sync.aligned.m8n8.x4.shared.b16 {%0,%1,%2,%3}, [%4];"
                 : "=r"(r[0]), "=r"(r[1]), "=r"(r[2]), "=r"(r[3]) : "r"(addr));
}

__device__ __forceinline__ void mma_f16(float* c, const uint32_t* a, const uint32_t* b) {
    asm volatile(
        "mma.sync.aligned.m16n8k16.row.col.f32.f16.f16.f32 "
        "{%0,%1,%2,%3}, {%4,%5,%6,%7}, {%8,%9}, {%0,%1,%2,%3};"
        : "+f"(c[0]), "+f"(c[1]), "+f"(c[2]), "+f"(c[3])
        : "r"(a[0]), "r"(a[1]), "r"(a[2]), "r"(a[3]), "r"(b[0]), "r"(b[1]));
}

#define CP_ASYNC16(dst, src) \
    asm volatile("cp.async.cg.shared.global [%0], [%1], 16;" :: "r"(dst), "l"(src) : "memory")
#define CP_COMMIT()  asm volatile("cp.async.commit_group;" ::: "memory")
#define CP_WAITG0()  asm volatile("cp.async.wait_group 0;" ::: "memory")
#define BAR_PAIR(id) asm volatile("bar.sync %0, 64;" :: "r"(id) : "memory")

// ---------------------------------------------------------------------------
// MUFU tanh
// ---------------------------------------------------------------------------
__device__ __forceinline__ float tanh_mufu(float x) {
    float xc = fminf(fmaxf(x, -9.0f), 9.0f);
    float e;
    asm("ex2.approx.f32 %0, %1;" : "=f"(e) : "f"(xc * 2.885390081777927f)); // e^{2x}
    float r;
    asm("rcp.approx.f32 %0, %1;" : "=f"(r) : "f"(e + 1.0f));
    return (e - 1.0f) * r;
}

// ---------------------------------------------------------------------------
// Kernel 0: coalesced SMEM tile transpose + fp16 convert of W1[:E]
// grid (16,16), block 256 (32x8)
// ---------------------------------------------------------------------------
__global__ void wprep_kernel(const float* __restrict__ W1) {
    __shared__ float tile[32][33];
    int tx = threadIdx.x & 31;
    int ty = threadIdx.x >> 5;                 // 0..7
    int e0 = blockIdx.x * 32;
    int k0 = blockIdx.y * 32;
#pragma unroll
    for (int j = 0; j < 32; j += 8)
        tile[ty + j][tx] = W1[(size_t)(k0 + ty + j) * E_ + e0 + tx];
    __syncthreads();
#pragma unroll
    for (int j = 0; j < 32; j += 8)
        g_Wt16[(size_t)(e0 + ty + j) * E_ + k0 + tx] =
            __float2half_rn(tile[tx][ty + j]);
}

// ---------------------------------------------------------------------------
// Kernel 1: qproj — grid (16, 8): W1[E:] read 8x not 64x
// ---------------------------------------------------------------------------
__global__ void qproj_kernel(const float* __restrict__ query,
                             const float* __restrict__ W1,
                             const float* __restrict__ b1) {
    __shared__ float qs[8][Q_];
    int tid = threadIdx.x;                      // 256
    int b0 = blockIdx.y * 8;
    int e  = blockIdx.x * 32 + (tid & 31);
    int bi = tid >> 5;
    {
        int r = tid >> 5;
        int c = (tid & 31) * 8;
#pragma unroll
        for (int u = 0; u < 8; u++)
            qs[r][c + u] = query[(b0 + r) * Q_ + c + u];
    }
    __syncthreads();
    float acc = b1[e];
#pragma unroll 8
    for (int q = 0; q < Q_; q++)
        acc = fmaf(qs[bi][q], W1[(size_t)(E_ + q) * E_ + e], acc);
    g_qproj[(b0 + bi) * E_ + e] = acc;
}

// ---------------------------------------------------------------------------
// Dummy pad kernel (positions logits at profiled launch index 3)
// ---------------------------------------------------------------------------
__global__ void dummy_pad_kernel() {
    if (threadIdx.x == 0) g_dummy_sink = 1;
}

// ---------------------------------------------------------------------------
// Kernel 2: tensor-core logits — UNCHANGED from R14 champion.
// ---------------------------------------------------------------------------
#define BM 64
#define NTILE 128

#define SM_W    0                       // [4 pair][2 stage][32 n][128B] = 32768
#define W_PAIR  8192
#define W_STAGE 4096
#define SM_A    32768                   // [64 rows][1024B] fp16 resident = 65536
#define SM_QV   98304                   // 512 floats
#define SM_VV   100352                  // 512 floats
#define SM_RED  102400                  // 256 floats
#define SMEM_GEMM 103424

__global__ void __launch_bounds__(256, 2)
logits_mma_kernel(const float* __restrict__ enc,
                  const float* __restrict__ v,
                  const int* __restrict__ length,
                  float* __restrict__ logits) {
    extern __shared__ char smem[];
    uint32_t smem_b = smem_u32_of(smem);
    const int tid  = threadIdx.x;
    const int lane = tid & 31;
    const int wid  = tid >> 5;
    const int mg   = wid & 1;
    const int ng   = wid >> 1;

    const int bid = blockIdx.x;     // 2048 CTAs
    const int b   = bid >> 5;
    const int l0  = (bid & 31) * BM;

    if (l0 >= length[b]) return;

    const int t = tid & 63;
    const int tng = tid >> 6;
    const __half* wsrc0 = g_Wt16 + (size_t)(tng * 32 + (t >> 1)) * E_ + (t & 1) * 32;
    uint32_t wdsts[4];
#pragma unroll
    for (int i = 0; i < 4; i++) {
        uint32_t u = (uint32_t)((t & 1) * 4 + i);
        wdsts[i] = smem_b + SM_W + (uint32_t)tng * W_PAIR + (uint32_t)(t >> 1) * 128
                 + ((u ^ ((uint32_t)(t >> 1) & 7)) << 4);
    }

#pragma unroll
    for (int i = 0; i < 4; i++)
        CP_ASYNC16(wdsts[i], wsrc0 + i * 8);
    CP_COMMIT();

    float* qv = reinterpret_cast<float*>(smem + SM_QV);
    float* vv = reinterpret_cast<float*>(smem + SM_VV);
    qv[tid]       = g_qproj[b * E_ + tid];
    qv[tid + 256] = g_qproj[b * E_ + tid + 256];
    vv[tid]       = v[tid];
    vv[tid + 256] = v[tid + 256];

    const float* Ag = enc + ((size_t)b * L_ + l0) * E_;
#pragma unroll
    for (int i = 0; i < 32; i++) {
        int idx = i * 256 + tid;
        int row = idx >> 7;
        int f4  = idx & 127;
        float4 a = *reinterpret_cast<const float4*>(Ag + (size_t)row * E_ + f4 * 4);
        __half2 h0 = __floats2half2_rn(a.x, a.y);
        __half2 h1 = __floats2half2_rn(a.z, a.w);
        uint32_t off = (uint32_t)(row * 1024)
                     + ((uint32_t)(((f4 >> 1) ^ (row & 7))) << 4) + (f4 & 1) * 8;
        *reinterpret_cast<__half2*>(smem + SM_A + off)     = h0;
        *reinterpret_cast<__half2*>(smem + SM_A + off + 4) = h1;
    }
    __syncthreads();

    const int  s7     = lane & 7;
    const int  lane16 = lane >> 4;
    const int  lane8  = (lane >> 3) & 1;
    const int  arow0  = mg * 32 + (lane & 15);
    const uint32_t abase0 = smem_b + SM_A + (uint32_t)arow0 * 1024;
    const uint32_t abase1 = abase0 + 16 * 1024;
    const int  nrl    = (lane & 7) + (lane16 << 3);
    const uint32_t wpair = smem_b + SM_W + (uint32_t)ng * W_PAIR;
    const uint32_t woff0 = (uint32_t)nrl * 128;
    const uint32_t woff1 = woff0 + 16 * 128;

    float acc[2][4][4];
    float lg[2][2] = {{0.f, 0.f}, {0.f, 0.f}};

    for (int nt = 0; nt < 4; nt++) {
#pragma unroll
        for (int mf = 0; mf < 2; mf++)
#pragma unroll
            for (int nf = 0; nf < 4; nf++)
#pragma unroll
                for (int e = 0; e < 4; e++) acc[mf][nf][e] = 0.0f;

#pragma unroll
        for (int kc = 0; kc < 8; kc++) {
            const int s = nt * 8 + kc;

            CP_WAITG0();
            BAR_PAIR(1 + ng);

            if (s + 1 < 32) {
                const int sn = s + 1;
                const uint32_t srcoff = (uint32_t)(sn >> 3) * 65536u
                                      + (uint32_t)(sn & 7) * 64u;
                const uint32_t stoff = (uint32_t)(sn & 1) * W_STAGE;
#pragma unroll
                for (int i = 0; i < 4; i++)
                    CP_ASYNC16(wdsts[i] + stoff, wsrc0 + srcoff + i * 8);
                CP_COMMIT();
            }

            const uint32_t wBase = wpair + (uint32_t)(s & 1) * W_STAGE;

#pragma unroll
            for (int ks = 0; ks < 4; ks++) {
                uint32_t aF0[4], aF1[4];
                {
                    uint32_t c = (uint32_t)(kc * 8 + ks * 2 + lane16);
                    uint32_t sw = (c ^ (uint32_t)s7) << 4;
                    ldsm4(aF0, abase0 + sw);
                    ldsm4(aF1, abase1 + sw);
                }
                uint32_t b0[4], b1[4];
                {
                    uint32_t c = (uint32_t)(ks * 2 + lane8);
                    uint32_t sw = (c ^ (uint32_t)(nrl & 7)) << 4;
                    ldsm4(b0, wBase + woff0 + sw);
                    ldsm4(b1, wBase + woff1 + sw);
                }
                mma_f16(acc[0][0], aF0, b0);
                mma_f16(acc[0][1], aF0, b0 + 2);
                mma_f16(acc[0][2], aF0, b1);
                mma_f16(acc[0][3], aF0, b1 + 2);
                mma_f16(acc[1][0], aF1, b0);
                mma_f16(acc[1][1], aF1, b0 + 2);
                mma_f16(acc[1][2], aF1, b1);
                mma_f16(acc[1][3], aF1, b1 + 2);
            }
        }

        {
            const int colb = nt * NTILE + ng * 32 + (lane & 3) * 2;
#pragma unroll
            for (int mf = 0; mf < 2; mf++) {
#pragma unroll
                for (int nf = 0; nf < 4; nf++) {
                    int col = colb + nf * 8;
                    float q0 = qv[col], q1 = qv[col + 1];
                    float w0 = vv[col], w1 = vv[col + 1];
                    lg[mf][0] += tanh_mufu(acc[mf][nf][0] + q0) * w0
                               + tanh_mufu(acc[mf][nf][1] + q1) * w1;
                    lg[mf][1] += tanh_mufu(acc[mf][nf][2] + q0) * w0
                               + tanh_mufu(acc[mf][nf][3] + q1) * w1;
                }
            }
        }
    }

    float* red = reinterpret_cast<float*>(smem + SM_RED);
#pragma unroll
    for (int mf = 0; mf < 2; mf++)
#pragma unroll
        for (int h = 0; h < 2; h++) {
            float x = lg[mf][h];
            x += __shfl_xor_sync(0xffffffffu, x, 1);
            x += __shfl_xor_sync(0xffffffffu, x, 2);
            lg[mf][h] = x;
        }
    if ((lane & 3) == 0) {
        int r = mg * 32 + (lane >> 2);
        red[ng * 64 + r]      = lg[0][0];
        red[ng * 64 + r + 8]  = lg[0][1];
        red[ng * 64 + r + 16] = lg[1][0];
        red[ng * 64 + r + 24] = lg[1][1];
    }
    __syncthreads();
    if (tid < 64) {
        logits[(size_t)b * L_ + l0 + tid] =
            red[tid] + red[64 + tid] + red[128 + tid] + red[192 + tid];
    }
}

// ---------------------------------------------------------------------------
// Kernel 3: masked softmax in place — 1024 threads (loop depth 2)
// ---------------------------------------------------------------------------
__global__ void softmax_kernel(float* __restrict__ att,
                               const int* __restrict__ length) {
    int b = blockIdx.x;
    int n = length[b];
    float* row = att + (size_t)b * L_;
    int tid = threadIdx.x;                 // 1024
    __shared__ float red[32];

    float x0 = row[tid];
    float x1 = row[tid + 1024];
    float m = NEGV;
    if (tid < n) m = x0;
    if (tid + 1024 < n) m = fmaxf(m, x1);
#pragma unroll
    for (int o = 16; o > 0; o >>= 1) m = fmaxf(m, __shfl_xor_sync(0xffffffffu, m, o));
    if ((tid & 31) == 0) red[tid >> 5] = m;
    __syncthreads();
    if (tid < 32) {
        float mm = red[tid];
#pragma unroll
        for (int o = 16; o > 0; o >>= 1) mm = fmaxf(mm, __shfl_xor_sync(0xffffffffu, mm, o));
        red[tid] = mm;
    }
    __syncthreads();
    m = red[0];
    __syncthreads();

    float e0 = (tid < n) ? expf(x0 - m) : 0.0f;
    float e1 = (tid + 1024 < n) ? expf(x1 - m) : 0.0f;
    float s = e0 + e1;
#pragma unroll
    for (int o = 16; o > 0; o >>= 1) s += __shfl_xor_sync(0xffffffffu, s, o);
    if ((tid & 31) == 0) red[tid >> 5] = s;
    __syncthreads();
    if (tid < 32) {
        float ss = red[tid];
#pragma unroll
        for (int o = 16; o > 0; o >>= 1) ss += __shfl_xor_sync(0xffffffffu, ss, o);
        red[tid] = ss;
    }
    __syncthreads();
    s = red[0];

    float inv = 1.0f / (s + EPS_);
    row[tid]        = e0 * inv;
    row[tid + 1024] = e1 * inv;
}

// ---------------------------------------------------------------------------
// Kernel 4: context partials (fp32 enc), NSPLIT=32 — R14 version
// ---------------------------------------------------------------------------
__global__ void ctx_partial_kernel(const float* __restrict__ enc,
                                   const float* __restrict__ att,
                                   const int* __restrict__ length) {
    int s = blockIdx.x;                    // 0..31
    int b = blockIdx.y;
    int t = threadIdx.x;                   // 128
    int n = length[b];
    int lbeg = s * (L_ / NSPLIT);
    int lend = lbeg + (L_ / NSPLIT);
    if (lend > n) lend = n;

    const float4* encb = reinterpret_cast<const float4*>(enc + (size_t)b * L_ * E_);
    const float* attb = att + (size_t)b * L_;
    float4 acc = make_float4(0.f, 0.f, 0.f, 0.f);
    int l = lbeg;
    for (; l + 4 <= lend; l += 4) {
#pragma unroll
        for (int u = 0; u < 4; u++) {
            float a = attb[l + u];
            float4 r = encb[(size_t)(l + u) * 128 + t];
            acc.x = fmaf(a, r.x, acc.x);
            acc.y = fmaf(a, r.y, acc.y);
            acc.z = fmaf(a, r.z, acc.z);
            acc.w = fmaf(a, r.w, acc.w);
        }
    }
    for (; l < lend; l++) {
        float a = attb[l];
        float4 r = encb[(size_t)l * 128 + t];
        acc.x = fmaf(a, r.x, acc.x);
        acc.y = fmaf(a, r.y, acc.y);
        acc.z = fmaf(a, r.z, acc.z);
        acc.w = fmaf(a, r.w, acc.w);
    }
    float4* outp = reinterpret_cast<float4*>(g_ctx_part + ((size_t)(b * NSPLIT + s)) * E_);
    outp[t] = acc;
}

// ---------------------------------------------------------------------------
// Kernel 5: reduce partials -> context
// ---------------------------------------------------------------------------
__global__ void ctx_reduce_kernel(float* __restrict__ context) {
    int b = blockIdx.x;
    int t = threadIdx.x;                   // 128
    float4 a = make_float4(0.f, 0.f, 0.f, 0.f);
#pragma unroll
    for (int s = 0; s < NSPLIT; s++) {
        const float4* p = reinterpret_cast<const float4*>(
            g_ctx_part + ((size_t)(b * NSPLIT + s)) * E_);
        float4 r = p[t];
        a.x += r.x; a.y += r.y; a.z += r.z; a.w += r.w;
    }
    reinterpret_cast<float4*>(context + (size_t)b * E_)[t] = a;
}

// ---------------------------------------------------------------------------
// launch
// ---------------------------------------------------------------------------
extern "C" void kernel_launch(void* const* d_in, const int* in_sizes, int n_in,
                              void* d_out, int out_size) {
    const float* enc   = (const float*)d_in[0];   // [B,L,E]
    const float* query = (const float*)d_in[1];   // [B,Q]
    const int*   len   = (const int*)  d_in[2];   // [B]
    const float* W1    = (const float*)d_in[3];   // [E+Q,E]
    const float* b1    = (const float*)d_in[4];   // [E]
    const float* v     = (const float*)d_in[5];   // [E]

    float* context = (float*)d_out;               // [B,E]
    float* att     = (float*)d_out + B_ * E_;     // [B,L]

    cudaFuncSetAttribute(logits_mma_kernel,
                         cudaFuncAttributeMaxDynamicSharedMemorySize, SMEM_GEMM);

    {
        dim3 g(16, 16);
        wprep_kernel<<<g, 256>>>(W1);                    // idx 0
    }
    {
        dim3 g(16, 8);
        qproj_kernel<<<g, 256>>>(query, W1, b1);         // idx 1
    }
    dummy_pad_kernel<<<1, 32>>>();                       // idx 2 (profiler pad)
    logits_mma_kernel<<<(B_ * L_) / BM, 256, SMEM_GEMM>>>(enc, v, len, att);  // idx 3
    softmax_kernel<<<B_, 1024>>>(att, len);              // idx 4
    {
        dim3 g(NSPLIT, B_);
        ctx_partial_kernel<<<g, 128>>>(enc, att, len);   // idx 5
    }
    ctx_reduce_kernel<<<B_, 128>>>(context);             // idx 6
}

// round 17
// speedup vs baseline: 1.0602x; 1.0169x over previous
#include <cuda_runtime.h>
#include <cuda_bf16.h>
#include <cuda_fp16.h>
#include <math.h>
#include <stdint.h>

#define B_   64
#define L_   2048
#define E_   512
#define Q_   256
#define NEGV -1000000000.0f
#define EPS_ 1e-5f
#define NSPLIT 32
#define SPLIT_ROWS (L_ / NSPLIT)    // 64

// ---------------------------------------------------------------------------
// device scratch (no allocations allowed)
// ---------------------------------------------------------------------------
__device__ float g_qproj[B_ * E_];
__device__ float g_ctx_part[B_ * NSPLIT * E_];
__device__ __align__(16) __half g_Wt16[E_ * E_];   // W1[:E]^T fp16 [e][k]
__device__ int g_ctx_cnt[B_];
__device__ int g_dummy_sink;

// ---------------------------------------------------------------------------
// PTX helpers
// ---------------------------------------------------------------------------
__device__ __forceinline__ uint32_t smem_u32_of(const void* p) {
    uint32_t a;
    asm("{ .reg .u64 t; cvta.to.shared.u64 t, %1; cvt.u32.u64 %0, t; }"
        : "=r"(a) : "l"(p));
    return a;
}

__device__ __forceinline__ void ldsm4(uint32_t* r, uint32_t addr) {
    asm volatile("ldmatrix.sync.aligned.m8n8.x4.shared.b16 {%0,%1,%2,%3}, [%4];"
                 : "=r"(r[0]), "=r"(r[1]), "=r"(r[2]), "=r"(r[3]) : "r"(addr));
}

__device__ __forceinline__ void mma_f16(float* c, const uint32_t* a, const uint32_t* b) {
    asm volatile(
        "mma.sync.aligned.m16n8k16.row.col.f32.f16.f16.f32 "
        "{%0,%1,%2,%3}, {%4,%5,%6,%7}, {%8,%9}, {%0,%1,%2,%3};"
        : "+f"(c[0]), "+f"(c[1]), "+f"(c[2]), "+f"(c[3])
        : "r"(a[0]), "r"(a[1]), "r"(a[2]), "r"(a[3]), "r"(b[0]), "r"(b[1]));
}

#define CP_ASYNC16(dst, src) \
    asm volatile("cp.async.cg.shared.global [%0], [%1], 16;" :: "r"(dst), "l"(src) : "memory")
#define CP_COMMIT()  asm volatile("cp.async.commit_group;" ::: "memory")
#define CP_WAITG0()  asm volatile("cp.async.wait_group 0;" ::: "memory")
#define BAR_PAIR(id) asm volatile("bar.sync %0, 64;" :: "r"(id) : "memory")

// ---------------------------------------------------------------------------
// MUFU tanh / exp
// ---------------------------------------------------------------------------
__device__ __forceinline__ float tanh_mufu(float x) {
    float xc = fminf(fmaxf(x, -9.0f), 9.0f);
    float e;
    asm("ex2.approx.f32 %0, %1;" : "=f"(e) : "f"(xc * 2.885390081777927f)); // e^{2x}
    float r;
    asm("rcp.approx.f32 %0, %1;" : "=f"(r) : "f"(e + 1.0f));
    return (e - 1.0f) * r;
}

__device__ __forceinline__ float exp_mufu(float x) {
    float e;
    asm("ex2.approx.f32 %0, %1;" : "=f"(e) : "f"(x * 1.4426950408889634f));
    return e;
}

// ---------------------------------------------------------------------------
// Kernel 0: coalesced SMEM tile transpose + fp16 convert of W1[:E]
// ---------------------------------------------------------------------------
__global__ void wprep_kernel(const float* __restrict__ W1) {
    __shared__ float tile[32][33];
    int tx = threadIdx.x & 31;
    int ty = threadIdx.x >> 5;
    int e0 = blockIdx.x * 32;
    int k0 = blockIdx.y * 32;
#pragma unroll
    for (int j = 0; j < 32; j += 8)
        tile[ty + j][tx] = W1[(size_t)(k0 + ty + j) * E_ + e0 + tx];
    __syncthreads();
#pragma unroll
    for (int j = 0; j < 32; j += 8)
        g_Wt16[(size_t)(e0 + ty + j) * E_ + k0 + tx] =
            __float2half_rn(tile[tx][ty + j]);
}

// ---------------------------------------------------------------------------
// Kernel 1: qproj — grid (16, 8)
// ---------------------------------------------------------------------------
__global__ void qproj_kernel(const float* __restrict__ query,
                             const float* __restrict__ W1,
                             const float* __restrict__ b1) {
    __shared__ float qs[8][Q_];
    int tid = threadIdx.x;                      // 256
    int b0 = blockIdx.y * 8;
    int e  = blockIdx.x * 32 + (tid & 31);
    int bi = tid >> 5;
    {
        int r = tid >> 5;
        int c = (tid & 31) * 8;
#pragma unroll
        for (int u = 0; u < 8; u++)
            qs[r][c + u] = query[(b0 + r) * Q_ + c + u];
    }
    __syncthreads();
    float acc = b1[e];
#pragma unroll 8
    for (int q = 0; q < Q_; q++)
        acc = fmaf(qs[bi][q], W1[(size_t)(E_ + q) * E_ + e], acc);
    g_qproj[(b0 + bi) * E_ + e] = acc;
}

// ---------------------------------------------------------------------------
// Kernel 2 (pad + counter reset): keeps logits at profiled idx 3
// ---------------------------------------------------------------------------
__global__ void reset_kernel() {
    if (threadIdx.x < B_) g_ctx_cnt[threadIdx.x] = 0;
    if (threadIdx.x == 0) g_dummy_sink = 1;
}

// ---------------------------------------------------------------------------
// Kernel 3: tensor-core logits — UNCHANGED from R14/R16 champion.
// ---------------------------------------------------------------------------
#define BM 64
#define NTILE 128

#define SM_W    0                       // [4 pair][2 stage][32 n][128B] = 32768
#define W_PAIR  8192
#define W_STAGE 4096
#define SM_A    32768                   // [64 rows][1024B] fp16 resident = 65536
#define SM_QV   98304                   // 512 floats
#define SM_VV   100352                  // 512 floats
#define SM_RED  102400                  // 256 floats
#define SMEM_GEMM 103424

__global__ void __launch_bounds__(256, 2)
logits_mma_kernel(const float* __restrict__ enc,
                  const float* __restrict__ v,
                  const int* __restrict__ length,
                  float* __restrict__ logits) {
    extern __shared__ char smem[];
    uint32_t smem_b = smem_u32_of(smem);
    const int tid  = threadIdx.x;
    const int lane = tid & 31;
    const int wid  = tid >> 5;
    const int mg   = wid & 1;
    const int ng   = wid >> 1;

    const int bid = blockIdx.x;     // 2048 CTAs
    const int b   = bid >> 5;
    const int l0  = (bid & 31) * BM;

    if (l0 >= length[b]) return;

    const int t = tid & 63;
    const int tng = tid >> 6;
    const __half* wsrc0 = g_Wt16 + (size_t)(tng * 32 + (t >> 1)) * E_ + (t & 1) * 32;
    uint32_t wdsts[4];
#pragma unroll
    for (int i = 0; i < 4; i++) {
        uint32_t u = (uint32_t)((t & 1) * 4 + i);
        wdsts[i] = smem_b + SM_W + (uint32_t)tng * W_PAIR + (uint32_t)(t >> 1) * 128
                 + ((u ^ ((uint32_t)(t >> 1) & 7)) << 4);
    }

#pragma unroll
    for (int i = 0; i < 4; i++)
        CP_ASYNC16(wdsts[i], wsrc0 + i * 8);
    CP_COMMIT();

    float* qv = reinterpret_cast<float*>(smem + SM_QV);
    float* vv = reinterpret_cast<float*>(smem + SM_VV);
    qv[tid]       = g_qproj[b * E_ + tid];
    qv[tid + 256] = g_qproj[b * E_ + tid + 256];
    vv[tid]       = v[tid];
    vv[tid + 256] = v[tid + 256];

    const float* Ag = enc + ((size_t)b * L_ + l0) * E_;
#pragma unroll
    for (int i = 0; i < 32; i++) {
        int idx = i * 256 + tid;
        int row = idx >> 7;
        int f4  = idx & 127;
        float4 a = *reinterpret_cast<const float4*>(Ag + (size_t)row * E_ + f4 * 4);
        __half2 h0 = __floats2half2_rn(a.x, a.y);
        __half2 h1 = __floats2half2_rn(a.z, a.w);
        uint32_t off = (uint32_t)(row * 1024)
                     + ((uint32_t)(((f4 >> 1) ^ (row & 7))) << 4) + (f4 & 1) * 8;
        *reinterpret_cast<__half2*>(smem + SM_A + off)     = h0;
        *reinterpret_cast<__half2*>(smem + SM_A + off + 4) = h1;
    }
    __syncthreads();

    const int  s7     = lane & 7;
    const int  lane16 = lane >> 4;
    const int  lane8  = (lane >> 3) & 1;
    const int  arow0  = mg * 32 + (lane & 15);
    const uint32_t abase0 = smem_b + SM_A + (uint32_t)arow0 * 1024;
    const uint32_t abase1 = abase0 + 16 * 1024;
    const int  nrl    = (lane & 7) + (lane16 << 3);
    const uint32_t wpair = smem_b + SM_W + (uint32_t)ng * W_PAIR;
    const uint32_t woff0 = (uint32_t)nrl * 128;
    const uint32_t woff1 = woff0 + 16 * 128;

    float acc[2][4][4];
    float lg[2][2] = {{0.f, 0.f}, {0.f, 0.f}};

    for (int nt = 0; nt < 4; nt++) {
#pragma unroll
        for (int mf = 0; mf < 2; mf++)
#pragma unroll
            for (int nf = 0; nf < 4; nf++)
#pragma unroll
                for (int e = 0; e < 4; e++) acc[mf][nf][e] = 0.0f;

#pragma unroll
        for (int kc = 0; kc < 8; kc++) {
            const int s = nt * 8 + kc;

            CP_WAITG0();
            BAR_PAIR(1 + ng);

            if (s + 1 < 32) {
                const int sn = s + 1;
                const uint32_t srcoff = (uint32_t)(sn >> 3) * 65536u
                                      + (uint32_t)(sn & 7) * 64u;
                const uint32_t stoff = (uint32_t)(sn & 1) * W_STAGE;
#pragma unroll
                for (int i = 0; i < 4; i++)
                    CP_ASYNC16(wdsts[i] + stoff, wsrc0 + srcoff + i * 8);
                CP_COMMIT();
            }

            const uint32_t wBase = wpair + (uint32_t)(s & 1) * W_STAGE;

#pragma unroll
            for (int ks = 0; ks < 4; ks++) {
                uint32_t aF0[4], aF1[4];
                {
                    uint32_t c = (uint32_t)(kc * 8 + ks * 2 + lane16);
                    uint32_t sw = (c ^ (uint32_t)s7) << 4;
                    ldsm4(aF0, abase0 + sw);
                    ldsm4(aF1, abase1 + sw);
                }
                uint32_t b0[4], b1[4];
                {
                    uint32_t c = (uint32_t)(ks * 2 + lane8);
                    uint32_t sw = (c ^ (uint32_t)(nrl & 7)) << 4;
                    ldsm4(b0, wBase + woff0 + sw);
                    ldsm4(b1, wBase + woff1 + sw);
                }
                mma_f16(acc[0][0], aF0, b0);
                mma_f16(acc[0][1], aF0, b0 + 2);
                mma_f16(acc[0][2], aF0, b1);
                mma_f16(acc[0][3], aF0, b1 + 2);
                mma_f16(acc[1][0], aF1, b0);
                mma_f16(acc[1][1], aF1, b0 + 2);
                mma_f16(acc[1][2], aF1, b1);
                mma_f16(acc[1][3], aF1, b1 + 2);
            }
        }

        {
            const int colb = nt * NTILE + ng * 32 + (lane & 3) * 2;
#pragma unroll
            for (int mf = 0; mf < 2; mf++) {
#pragma unroll
                for (int nf = 0; nf < 4; nf++) {
                    int col = colb + nf * 8;
                    float q0 = qv[col], q1 = qv[col + 1];
                    float w0 = vv[col], w1 = vv[col + 1];
                    lg[mf][0] += tanh_mufu(acc[mf][nf][0] + q0) * w0
                               + tanh_mufu(acc[mf][nf][1] + q1) * w1;
                    lg[mf][1] += tanh_mufu(acc[mf][nf][2] + q0) * w0
                               + tanh_mufu(acc[mf][nf][3] + q1) * w1;
                }
            }
        }
    }

    float* red = reinterpret_cast<float*>(smem + SM_RED);
#pragma unroll
    for (int mf = 0; mf < 2; mf++)
#pragma unroll
        for (int h = 0; h < 2; h++) {
            float x = lg[mf][h];
            x += __shfl_xor_sync(0xffffffffu, x, 1);
            x += __shfl_xor_sync(0xffffffffu, x, 2);
            lg[mf][h] = x;
        }
    if ((lane & 3) == 0) {
        int r = mg * 32 + (lane >> 2);
        red[ng * 64 + r]      = lg[0][0];
        red[ng * 64 + r + 8]  = lg[0][1];
        red[ng * 64 + r + 16] = lg[1][0];
        red[ng * 64 + r + 24] = lg[1][1];
    }
    __syncthreads();
    if (tid < 64) {
        logits[(size_t)b * L_ + l0 + tid] =
            red[tid] + red[64 + tid] + red[128 + tid] + red[192 + tid];
    }
}

// ---------------------------------------------------------------------------
// Kernel 4: FUSED softmax + context partial + last-block reduce.
// grid (NSPLIT, B_), 128 threads. Each block:
//   1) reads the full logits row (L2), computes masked max & exp-sum
//   2) writes att for its 64-row slice (exact 0 beyond length)
//   3) accumulates its ctx partial over valid rows
//   4) last-arriving block per b reduces the 32 partials -> context
// ---------------------------------------------------------------------------
__global__ void ctx_fused_kernel(const float* __restrict__ enc,
                                 const int* __restrict__ length,
                                 float* __restrict__ att,
                                 float* __restrict__ context) {
    __shared__ float red[4];
    __shared__ float att_s[SPLIT_ROWS];
    __shared__ float stat[2];                 // m, inv

    const int s = blockIdx.x;                 // 0..31
    const int b = blockIdx.y;
    const int t = threadIdx.x;                // 128
    const int lane = t & 31;
    const int n = length[b];
    float* row = att + (size_t)b * L_;

    // ---- softmax stats over the full row (16 values per thread) ----
    float xv[16];
    float m = NEGV;
#pragma unroll
    for (int i = 0; i < 16; i++) {
        int l = t + i * 128;
        float x = row[l];
        xv[i] = x;
        if (l < n) m = fmaxf(m, x);
    }
#pragma unroll
    for (int o = 16; o > 0; o >>= 1) m = fmaxf(m, __shfl_xor_sync(0xffffffffu, m, o));
    if (lane == 0) red[t >> 5] = m;
    __syncthreads();
    m = fmaxf(fmaxf(red[0], red[1]), fmaxf(red[2], red[3]));
    __syncthreads();

    float ssum = 0.0f;
#pragma unroll
    for (int i = 0; i < 16; i++) {
        int l = t + i * 128;
        if (l < n) ssum += exp_mufu(xv[i] - m);
    }
#pragma unroll
    for (int o = 16; o > 0; o >>= 1) ssum += __shfl_xor_sync(0xffffffffu, ssum, o);
    if (lane == 0) red[t >> 5] = ssum;
    __syncthreads();
    if (t == 0) {
        float sm = red[0] + red[1] + red[2] + red[3];
        stat[0] = m;
        stat[1] = 1.0f / (sm + EPS_);
    }
    __syncthreads();
    m = stat[0];
    const float inv = stat[1];

    // ---- write att slice + stash in SMEM ----
    const int lbeg = s * SPLIT_ROWS;
    {
        // 64 rows, 128 threads: threads 0..63 handle one row each
        if (t < SPLIT_ROWS) {
            int l = lbeg + t;
            float e = (l < n) ? exp_mufu(row[l] - m) * inv : 0.0f;
            att_s[t] = e;
            row[l] = e;
        }
    }
    __syncthreads();

    // ---- ctx partial over valid rows of this slice ----
    int lend = lbeg + SPLIT_ROWS;
    if (lend > n) lend = n;
    const float4* encb = reinterpret_cast<const float4*>(enc + (size_t)b * L_ * E_);
    float4 acc = make_float4(0.f, 0.f, 0.f, 0.f);
    int l = lbeg;
    for (; l + 4 <= lend; l += 4) {
#pragma unroll
        for (int u = 0; u < 4; u++) {
            float a = att_s[l - lbeg + u];
            float4 r = encb[(size_t)(l + u) * 128 + t];
            acc.x = fmaf(a, r.x, acc.x);
            acc.y = fmaf(a, r.y, acc.y);
            acc.z = fmaf(a, r.z, acc.z);
            acc.w = fmaf(a, r.w, acc.w);
        }
    }
    for (; l < lend; l++) {
        float a = att_s[l - lbeg];
        float4 r = encb[(size_t)l * 128 + t];
        acc.x = fmaf(a, r.x, acc.x);
        acc.y = fmaf(a, r.y, acc.y);
        acc.z = fmaf(a, r.z, acc.z);
        acc.w = fmaf(a, r.w, acc.w);
    }
    reinterpret_cast<float4*>(g_ctx_part + ((size_t)(b * NSPLIT + s)) * E_)[t] = acc;

    // ---- last block per b reduces ----
    __threadfence();
    __shared__ int is_last;
    __syncthreads();
    if (t == 0) is_last = (atomicAdd(&g_ctx_cnt[b], 1) == NSPLIT - 1);
    __syncthreads();
    if (is_last) {
        float4 a = make_float4(0.f, 0.f, 0.f, 0.f);
#pragma unroll 8
        for (int ss = 0; ss < NSPLIT; ss++) {
            float4 r = reinterpret_cast<const float4*>(
                g_ctx_part + ((size_t)(b * NSPLIT + ss)) * E_)[t];
            a.x += r.x; a.y += r.y; a.z += r.z; a.w += r.w;
        }
        reinterpret_cast<float4*>(context + (size_t)b * E_)[t] = a;
    }
}

// ---------------------------------------------------------------------------
// launch
// ---------------------------------------------------------------------------
extern "C" void kernel_launch(void* const* d_in, const int* in_sizes, int n_in,
                              void* d_out, int out_size) {
    const float* enc   = (const float*)d_in[0];   // [B,L,E]
    const float* query = (const float*)d_in[1];   // [B,Q]
    const int*   len   = (const int*)  d_in[2];   // [B]
    const float* W1    = (const float*)d_in[3];   // [E+Q,E]
    const float* b1    = (const float*)d_in[4];   // [E]
    const float* v     = (const float*)d_in[5];   // [E]

    float* context = (float*)d_out;               // [B,E]
    float* att     = (float*)d_out + B_ * E_;     // [B,L]

    cudaFuncSetAttribute(logits_mma_kernel,
                         cudaFuncAttributeMaxDynamicSharedMemorySize, SMEM_GEMM);

    {
        dim3 g(16, 16);
        wprep_kernel<<<g, 256>>>(W1);                    // idx 0
    }
    {
        dim3 g(16, 8);
        qproj_kernel<<<g, 256>>>(query, W1, b1);         // idx 1
    }
    reset_kernel<<<1, 64>>>();                           // idx 2 (pad + reset)
    logits_mma_kernel<<<(B_ * L_) / BM, 256, SMEM_GEMM>>>(enc, v, len, att);  // idx 3
    {
        dim3 g(NSPLIT, B_);
        ctx_fused_kernel<<<g, 128>>>(enc, len, att, context);  // idx 4
    }
}